// round 14
// baseline (speedup 1.0000x reference)
#include <cuda_runtime.h>
#include <cuda_fp16.h>
#include <math.h>

#define N_NODES 100000
#define N_EDGES 1200000
#define HID 64
#define NTOT (2 * N_NODES)
#define NB2 196   // ceil(200000/1024)

typedef unsigned long long ull;

// ---------------- scratch (device globals, no allocation) ----------------
__device__ __half2 g_H[2 * (size_t)N_NODES * 32];   // H in fp16 (32 half2 per row)
__device__ float   g_Z[2 * (size_t)N_NODES * HID];  // post-SELU activations (fp32)
__device__ int   g_rowptr[NTOT + 1];
__device__ int2  g_edge[2 * N_EDGES];    // sorted (col, val-bits) per dest row
__device__ int   g_cnt[NTOT];
__device__ int   g_bsums[NB2 + 1];

// ---------------- packed fp32 helpers ----------------
__device__ __forceinline__ void ffma2(ull& c, ull a, ull b) {
    asm("fma.rn.f32x2 %0, %1, %2, %0;" : "+l"(c) : "l"(a), "l"(b));
}
__device__ __forceinline__ ull pack2(float x, float y) {
    ull r;
    asm("mov.b64 %0, {%1, %2};" : "=l"(r) : "f"(x), "f"(y));
    return r;
}

// ---------------- CSR build (both graphs at once) ----------------
__global__ void zero_cnt_kernel() {
    int i = blockIdx.x * 256 + threadIdx.x;
    if (i < NTOT) g_cnt[i] = 0;
}

__global__ void edge_count_kernel(const int* __restrict__ rows1,
                                  const int* __restrict__ rows2) {
    int e = blockIdx.x * 256 + threadIdx.x;
    if (e < 2 * N_EDGES) {
        int g = e >= N_EDGES;
        int le = e - g * N_EDGES;
        int r = g ? rows2[le] : rows1[le];
        atomicAdd(&g_cnt[g * N_NODES + r], 1);
    }
}

__global__ void scan_reduce_kernel() {
    __shared__ int s[256];
    int t = threadIdx.x;
    int base = blockIdx.x * 1024 + t * 4;
    int v = 0;
#pragma unroll
    for (int i = 0; i < 4; i++) {
        int idx = base + i;
        if (idx < NTOT) v += g_cnt[idx];
    }
    s[t] = v;
    __syncthreads();
    for (int o = 128; o; o >>= 1) {
        if (t < o) s[t] += s[t + o];
        __syncthreads();
    }
    if (t == 0) g_bsums[blockIdx.x] = s[0];
}

__global__ void scan_bsums_kernel() {
    __shared__ int s[2][256];
    int t = threadIdx.x;
    int v = (t < NB2) ? g_bsums[t] : 0;
    int buf = 0;
    s[0][t] = v;
    __syncthreads();
    for (int o = 1; o < 256; o <<= 1) {
        int x = s[buf][t];
        if (t >= o) x += s[buf][t - o];
        s[buf ^ 1][t] = x;
        buf ^= 1;
        __syncthreads();
    }
    int inc = s[buf][t];
    if (t < NB2) g_bsums[t] = inc - v;   // exclusive
    if (t == 255) g_bsums[NB2] = inc;    // total
}

__global__ void scan_final_kernel() {
    __shared__ int s[2][256];
    int t = threadIdx.x;
    int base = blockIdx.x * 1024 + t * 4;
    int v[4];
#pragma unroll
    for (int i = 0; i < 4; i++)
        v[i] = (base + i < NTOT) ? g_cnt[base + i] : 0;
    int tot = v[0] + v[1] + v[2] + v[3];
    int buf = 0;
    s[0][t] = tot;
    __syncthreads();
    for (int o = 1; o < 256; o <<= 1) {
        int x = s[buf][t];
        if (t >= o) x += s[buf][t - o];
        s[buf ^ 1][t] = x;
        buf ^= 1;
        __syncthreads();
    }
    int run = s[buf][t] - tot + g_bsums[blockIdx.x];
#pragma unroll
    for (int i = 0; i < 4; i++) {
        if (base + i < NTOT) {
            g_rowptr[base + i] = run;
            g_cnt[base + i] = 0;          // fused re-zero for the scatter pass
        }
        run += v[i];
    }
    if (blockIdx.x == 0 && t == 0) g_rowptr[NTOT] = g_bsums[NB2];
}

__global__ void edge_scatter_kernel(const int* __restrict__ rows1,
                                    const int* __restrict__ cols1,
                                    const float* __restrict__ vals1,
                                    const int* __restrict__ rows2,
                                    const int* __restrict__ cols2,
                                    const float* __restrict__ vals2) {
    int e = blockIdx.x * 256 + threadIdx.x;
    if (e < 2 * N_EDGES) {
        int g = e >= N_EDGES;
        int le = e - g * N_EDGES;
        int r, c; float v;
        if (g) { r = rows2[le]; c = cols2[le]; v = vals2[le]; }
        else   { r = rows1[le]; c = cols1[le]; v = vals1[le]; }
        int key = g * N_NODES + r;
        int p = g_rowptr[key] + atomicAdd(&g_cnt[key], 1);
        g_edge[p] = make_int2(c, __float_as_int(v));
    }
}

// ---------------- GEMM: H[g] = A[g] @ B[K x 64], fp16 output ----------------
// BM=128, BN=64, BK=16, 256 threads, 8 rows x 4 cols per thread, FFMA2 inner,
// register prefetch of the next gmem tile. (Proven R4/R8/R10 configuration.)
__global__ __launch_bounds__(256) void gemm128_kernel(const float* __restrict__ X1,
                                                      const float* __restrict__ X2,
                                                      int use_z,
                                                      const float* __restrict__ B,
                                                      int K, int gbase) {
    int g = gbase + blockIdx.y;
    const float* __restrict__ A =
        use_z ? (g_Z + (size_t)g * N_NODES * HID) : (g ? X2 : X1);
    __half2* __restrict__ Hout = g_H + (size_t)g * N_NODES * 32;

    __shared__ float As[16][132];   // [k][m], row stride 528B (16B aligned)
    __shared__ float Bs[16][64];    // [k][n]
    int tid = threadIdx.x;
    int tx = tid & 15, ty = tid >> 4;
    int row0 = blockIdx.x * 128;

    // gmem load assignment
    int am = tid >> 1;            // 0..127: A row within tile
    int af = (tid & 1) * 8;       // k offset within BK: 0 or 8 (two float4s)
    int bk = tid >> 4;            // 0..15
    int bn = (tid & 15) * 4;
    int arow = row0 + am;
    bool a_ok = arow < N_NODES;
    const float* Abase = A + (size_t)arow * K;

    ull acc[8][2];
#pragma unroll
    for (int i = 0; i < 8; i++) { acc[i][0] = 0ull; acc[i][1] = 0ull; }

    float4 pa0, pa1, pb;
    // prologue: load tile 0
    pa0 = a_ok ? *(const float4*)&Abase[af]     : make_float4(0, 0, 0, 0);
    pa1 = a_ok ? *(const float4*)&Abase[af + 4] : make_float4(0, 0, 0, 0);
    pb  = *(const float4*)&B[bk * 64 + bn];

    for (int k0 = 0; k0 < K; k0 += 16) {
        // commit prefetched tile to smem
        As[af + 0][am] = pa0.x; As[af + 1][am] = pa0.y;
        As[af + 2][am] = pa0.z; As[af + 3][am] = pa0.w;
        As[af + 4][am] = pa1.x; As[af + 5][am] = pa1.y;
        As[af + 6][am] = pa1.z; As[af + 7][am] = pa1.w;
        *(float4*)&Bs[bk][bn] = pb;
        __syncthreads();

        // prefetch next tile (overlaps compute)
        if (k0 + 16 < K) {
            pa0 = a_ok ? *(const float4*)&Abase[k0 + 16 + af]     : make_float4(0, 0, 0, 0);
            pa1 = a_ok ? *(const float4*)&Abase[k0 + 16 + af + 4] : make_float4(0, 0, 0, 0);
            pb  = *(const float4*)&B[(k0 + 16 + bk) * 64 + bn];
        }

#pragma unroll
        for (int kk = 0; kk < 16; kk++) {
            float4 a4 = *(const float4*)&As[kk][ty * 8];
            float4 a8 = *(const float4*)&As[kk][ty * 8 + 4];
            ulonglong2 bv = *(const ulonglong2*)&Bs[kk][tx * 4];
            ull ad;
            ad = pack2(a4.x, a4.x); ffma2(acc[0][0], ad, bv.x); ffma2(acc[0][1], ad, bv.y);
            ad = pack2(a4.y, a4.y); ffma2(acc[1][0], ad, bv.x); ffma2(acc[1][1], ad, bv.y);
            ad = pack2(a4.z, a4.z); ffma2(acc[2][0], ad, bv.x); ffma2(acc[2][1], ad, bv.y);
            ad = pack2(a4.w, a4.w); ffma2(acc[3][0], ad, bv.x); ffma2(acc[3][1], ad, bv.y);
            ad = pack2(a8.x, a8.x); ffma2(acc[4][0], ad, bv.x); ffma2(acc[4][1], ad, bv.y);
            ad = pack2(a8.y, a8.y); ffma2(acc[5][0], ad, bv.x); ffma2(acc[5][1], ad, bv.y);
            ad = pack2(a8.z, a8.z); ffma2(acc[6][0], ad, bv.x); ffma2(acc[6][1], ad, bv.y);
            ad = pack2(a8.w, a8.w); ffma2(acc[7][0], ad, bv.x); ffma2(acc[7][1], ad, bv.y);
        }
        __syncthreads();
    }
#pragma unroll
    for (int i = 0; i < 8; i++) {
        int row = row0 + ty * 8 + i;
        if (row < N_NODES) {
            float2 f01 = *(float2*)&acc[i][0];
            float2 f23 = *(float2*)&acc[i][1];
            __half2 h0 = __floats2half2_rn(f01.x, f01.y);
            __half2 h1 = __floats2half2_rn(f23.x, f23.y);
            uint2 v;
            v.x = *(unsigned int*)&h0;
            v.y = *(unsigned int*)&h1;
            *(uint2*)&Hout[(size_t)row * 32 + tx * 2] = v;
        }
    }
}

// ---------------- SPMM: shuffle-distributed edges + MLP-16 H gather ----------
__device__ __forceinline__ float warp_sum(float v) {
#pragma unroll
    for (int o = 16; o; o >>= 1) v += __shfl_xor_sync(0xffffffffu, v, o);
    return v;
}

// MODE 0: Z[g] = SELU(A@H + b) ; MODE 1: out[g] = rownorm(A@H + b)
template <int MODE>
__global__ __launch_bounds__(256) void spmm_kernel(const float* __restrict__ bias,
                                                   float* __restrict__ out_ext,
                                                   int gbase) {
    int g = gbase + blockIdx.y;
    int warp = threadIdx.x >> 5, lane = threadIdx.x & 31;
    int row = blockIdx.x * 8 + warp;
    if (row >= N_NODES) return;
    const __half2* __restrict__ H = g_H + (size_t)g * N_NODES * 32;
    int key = g * N_NODES + row;
    int s = g_rowptr[key], e = g_rowptr[key + 1];
    int deg = e - s;
    float bx = __ldg(&bias[lane * 2]);
    float by = __ldg(&bias[lane * 2 + 1]);
    float ax = 0.f, ay = 0.f;

    if (deg > 0) {
        // one coalesced trip fetches the first up-to-32 edges across lanes
        int2 myed = g_edge[s + (lane < deg ? lane : 0)];
        int n1 = deg < 32 ? deg : 32;

        // edges 0..15: distribute via shuffle, gather H at MLP=16
        {
            int   cc[16];
            float vv[16];
#pragma unroll
            for (int i = 0; i < 16; i++) {
                cc[i] = __shfl_sync(0xffffffffu, myed.x, i);
                vv[i] = __int_as_float(__shfl_sync(0xffffffffu, myed.y, i));
            }
            __half2 h[16];
#pragma unroll
            for (int i = 0; i < 16; i++)
                h[i] = H[(size_t)cc[i] * 32 + lane];
#pragma unroll
            for (int i = 0; i < 16; i++) {
                float v = (i < n1) ? vv[i] : 0.f;
                float2 f = __half22float2(h[i]);
                ax += v * f.x;
                ay += v * f.y;
            }
        }
        // edges 16..31
        if (deg > 16) {
            int   cc[16];
            float vv[16];
#pragma unroll
            for (int i = 0; i < 16; i++) {
                cc[i] = __shfl_sync(0xffffffffu, myed.x, 16 + i);
                vv[i] = __int_as_float(__shfl_sync(0xffffffffu, myed.y, 16 + i));
            }
            __half2 h[16];
#pragma unroll
            for (int i = 0; i < 16; i++)
                h[i] = H[(size_t)cc[i] * 32 + lane];
#pragma unroll
            for (int i = 0; i < 16; i++) {
                float v = (16 + i < n1) ? vv[i] : 0.f;
                float2 f = __half22float2(h[i]);
                ax += v * f.x;
                ay += v * f.y;
            }
        }
        // rare tail: deg > 32, batched memory path
        for (int j = s + 32; j < e; j += 8) {
            int2 e8[8];
#pragma unroll
            for (int i = 0; i < 8; i++) {
                int idx = j + i;
                e8[i] = g_edge[idx < e ? idx : s];
            }
            __half2 h8[8];
#pragma unroll
            for (int i = 0; i < 8; i++)
                h8[i] = H[(size_t)e8[i].x * 32 + lane];
#pragma unroll
            for (int i = 0; i < 8; i++) {
                float v = (j + i < e) ? __int_as_float(e8[i].y) : 0.f;
                float2 f = __half22float2(h8[i]);
                ax += v * f.x;
                ay += v * f.y;
            }
        }
    }

    ax += bx;
    ay += by;
    if (MODE == 0) {
        const float sc = 1.0507009873554805f, al = 1.6732632423543772f;
        ax = ax > 0.f ? sc * ax : sc * al * expm1f(ax);
        ay = ay > 0.f ? sc * ay : sc * al * expm1f(ay);
        float2 o = {ax, ay};
        *(float2*)&g_Z[((size_t)g * N_NODES + row) * HID + lane * 2] = o;
    } else {
        float ss = warp_sum(ax * ax + ay * ay);
        float inv = 1.f / fmaxf(sqrtf(ss), 1e-12f);
        float2 o = {ax * inv, ay * inv};
        *(float2*)&out_ext[((size_t)g * N_NODES + row) * HID + lane * 2] = o;
    }
}

// ---------------- launch (R10 multi-stream overlap) ----------------
extern "C" void kernel_launch(void* const* d_in, const int* in_sizes, int n_in,
                              void* d_out, int out_size) {
    const float* X1 = (const float*)d_in[0];
    const float* X2 = (const float*)d_in[1];
    const int*   rows1 = (const int*)d_in[2];
    const int*   cols1 = (const int*)d_in[3];
    const float* vals1 = (const float*)d_in[4];
    const int*   rows2 = (const int*)d_in[5];
    const int*   cols2 = (const int*)d_in[6];
    const float* vals2 = (const float*)d_in[7];
    const float* W1 = (const float*)d_in[8];
    const float* b1 = (const float*)d_in[9];
    const float* W2 = (const float*)d_in[10];
    const float* b2 = (const float*)d_in[11];
    float* out = (float*)d_out;

    // Aux streams/events: created once on the first (uncaptured, untimed)
    // correctness call; reused on every call. Identical work every call.
    static cudaStream_t sB = nullptr, sC = nullptr;
    static cudaEvent_t evRoot = nullptr, evCsr = nullptr, evG1 = nullptr, evB = nullptr;
    if (sB == nullptr) {
        cudaStreamCreateWithFlags(&sB, cudaStreamNonBlocking);
        cudaStreamCreateWithFlags(&sC, cudaStreamNonBlocking);
        cudaEventCreateWithFlags(&evRoot, cudaEventDisableTiming);
        cudaEventCreateWithFlags(&evCsr, cudaEventDisableTiming);
        cudaEventCreateWithFlags(&evG1, cudaEventDisableTiming);
        cudaEventCreateWithFlags(&evB, cudaEventDisableTiming);
    }

    const int ZG = (NTOT + 255) / 256;          // 782
    const int EG = (2 * N_EDGES + 255) / 256;   // 9375
    dim3 GG2((N_NODES + 127) / 128, 2);         // gemm1, both graphs
    dim3 GG1((N_NODES + 127) / 128, 1);         // gemm2, per graph
    dim3 SG1((N_NODES + 7) / 8, 1);             // spmm, per graph

    // fork: CSR chain on sC, gemm1 on main stream (concurrent)
    cudaEventRecord(evRoot, 0);
    cudaStreamWaitEvent(sC, evRoot, 0);

    zero_cnt_kernel<<<ZG, 256, 0, sC>>>();
    edge_count_kernel<<<EG, 256, 0, sC>>>(rows1, rows2);
    scan_reduce_kernel<<<NB2, 256, 0, sC>>>();

    gemm128_kernel<<<GG2, 256>>>(X1, X2, 0, W1, 256, 0);   // H = X @ W1 (main)
    cudaEventRecord(evG1, 0);

    scan_bsums_kernel<<<1, 256, 0, sC>>>();
    scan_final_kernel<<<NB2, 256, 0, sC>>>();              // also re-zeroes g_cnt
    edge_scatter_kernel<<<EG, 256, 0, sC>>>(rows1, cols1, vals1, rows2, cols2, vals2);
    cudaEventRecord(evCsr, sC);

    // graph-1 chain on sB (needs gemm1 + CSR)
    cudaStreamWaitEvent(sB, evCsr, 0);
    cudaStreamWaitEvent(sB, evG1, 0);
    spmm_kernel<0><<<SG1, 256, 0, sB>>>(b1, nullptr, 1);
    gemm128_kernel<<<GG1, 256, 0, sB>>>(X1, X2, 1, W2, HID, 1);
    spmm_kernel<1><<<SG1, 256, 0, sB>>>(b2, out, 1);
    cudaEventRecord(evB, sB);

    // graph-0 chain on main stream (needs gemm1 [ordered] + CSR)
    cudaStreamWaitEvent(0, evCsr, 0);
    spmm_kernel<0><<<SG1, 256>>>(b1, nullptr, 0);
    gemm128_kernel<<<GG1, 256>>>(X1, X2, 1, W2, HID, 0);
    spmm_kernel<1><<<SG1, 256>>>(b2, out, 0);

    // join
    cudaStreamWaitEvent(0, evB, 0);
}

// round 15
// speedup vs baseline: 1.0690x; 1.0690x over previous
#include <cuda_runtime.h>
#include <cuda_fp16.h>
#include <math.h>

#define N_NODES 100000
#define N_EDGES 1200000
#define HID 64
#define NTOT (2 * N_NODES)
#define NB2 196   // ceil(200000/1024)

typedef unsigned long long ull;

// ---------------- scratch (device globals, no allocation) ----------------
__device__ __half2 g_H[2 * (size_t)N_NODES * 32];   // H in fp16 (32 half2 per row)
__device__ float   g_Z[2 * (size_t)N_NODES * HID];  // post-SELU activations (fp32)
__device__ int   g_rowptr[NTOT + 1];
__device__ int2  g_edge[2 * N_EDGES];    // sorted (col, val-bits) per dest row
__device__ int   g_cnt[NTOT];
__device__ int   g_bsums[NB2 + 1];

// ---------------- packed fp32 helpers ----------------
__device__ __forceinline__ void ffma2(ull& c, ull a, ull b) {
    asm("fma.rn.f32x2 %0, %1, %2, %0;" : "+l"(c) : "l"(a), "l"(b));
}
__device__ __forceinline__ ull pack2(float x, float y) {
    ull r;
    asm("mov.b64 %0, {%1, %2};" : "=l"(r) : "f"(x), "f"(y));
    return r;
}

// ---------------- CSR build (both graphs at once) ----------------
__global__ void zero_cnt_kernel() {
    int i = blockIdx.x * 256 + threadIdx.x;
    if (i < NTOT) g_cnt[i] = 0;
}

__global__ void edge_count_kernel(const int* __restrict__ rows1,
                                  const int* __restrict__ rows2) {
    int e = blockIdx.x * 256 + threadIdx.x;
    if (e < 2 * N_EDGES) {
        int g = e >= N_EDGES;
        int le = e - g * N_EDGES;
        int r = g ? rows2[le] : rows1[le];
        atomicAdd(&g_cnt[g * N_NODES + r], 1);
    }
}

__global__ void scan_reduce_kernel() {
    __shared__ int s[256];
    int t = threadIdx.x;
    int base = blockIdx.x * 1024 + t * 4;
    int v = 0;
#pragma unroll
    for (int i = 0; i < 4; i++) {
        int idx = base + i;
        if (idx < NTOT) v += g_cnt[idx];
    }
    s[t] = v;
    __syncthreads();
    for (int o = 128; o; o >>= 1) {
        if (t < o) s[t] += s[t + o];
        __syncthreads();
    }
    if (t == 0) g_bsums[blockIdx.x] = s[0];
}

__global__ void scan_bsums_kernel() {
    __shared__ int s[2][256];
    int t = threadIdx.x;
    int v = (t < NB2) ? g_bsums[t] : 0;
    int buf = 0;
    s[0][t] = v;
    __syncthreads();
    for (int o = 1; o < 256; o <<= 1) {
        int x = s[buf][t];
        if (t >= o) x += s[buf][t - o];
        s[buf ^ 1][t] = x;
        buf ^= 1;
        __syncthreads();
    }
    int inc = s[buf][t];
    if (t < NB2) g_bsums[t] = inc - v;   // exclusive
    if (t == 255) g_bsums[NB2] = inc;    // total
}

__global__ void scan_final_kernel() {
    __shared__ int s[2][256];
    int t = threadIdx.x;
    int base = blockIdx.x * 1024 + t * 4;
    int v[4];
#pragma unroll
    for (int i = 0; i < 4; i++)
        v[i] = (base + i < NTOT) ? g_cnt[base + i] : 0;
    int tot = v[0] + v[1] + v[2] + v[3];
    int buf = 0;
    s[0][t] = tot;
    __syncthreads();
    for (int o = 1; o < 256; o <<= 1) {
        int x = s[buf][t];
        if (t >= o) x += s[buf][t - o];
        s[buf ^ 1][t] = x;
        buf ^= 1;
        __syncthreads();
    }
    int run = s[buf][t] - tot + g_bsums[blockIdx.x];
#pragma unroll
    for (int i = 0; i < 4; i++) {
        if (base + i < NTOT) {
            g_rowptr[base + i] = run;
            g_cnt[base + i] = 0;          // fused re-zero for the scatter pass
        }
        run += v[i];
    }
    if (blockIdx.x == 0 && t == 0) g_rowptr[NTOT] = g_bsums[NB2];
}

__global__ void edge_scatter_kernel(const int* __restrict__ rows1,
                                    const int* __restrict__ cols1,
                                    const float* __restrict__ vals1,
                                    const int* __restrict__ rows2,
                                    const int* __restrict__ cols2,
                                    const float* __restrict__ vals2) {
    int e = blockIdx.x * 256 + threadIdx.x;
    if (e < 2 * N_EDGES) {
        int g = e >= N_EDGES;
        int le = e - g * N_EDGES;
        int r, c; float v;
        if (g) { r = rows2[le]; c = cols2[le]; v = vals2[le]; }
        else   { r = rows1[le]; c = cols1[le]; v = vals1[le]; }
        int key = g * N_NODES + r;
        int p = g_rowptr[key] + atomicAdd(&g_cnt[key], 1);
        g_edge[p] = make_int2(c, __float_as_int(v));
    }
}

// ---------------- GEMM: H[g] = A[g] @ B[K x 64], fp16 output ----------------
// BM=128, BN=64, BK=16, 256 threads, 8 rows x 4 cols per thread, FFMA2 inner,
// register prefetch of the next gmem tile. (Proven R4/R8/R10 configuration.)
__global__ __launch_bounds__(256) void gemm128_kernel(const float* __restrict__ X1,
                                                      const float* __restrict__ X2,
                                                      int use_z,
                                                      const float* __restrict__ B,
                                                      int K, int gbase) {
    int g = gbase + blockIdx.y;
    const float* __restrict__ A =
        use_z ? (g_Z + (size_t)g * N_NODES * HID) : (g ? X2 : X1);
    __half2* __restrict__ Hout = g_H + (size_t)g * N_NODES * 32;

    __shared__ float As[16][132];   // [k][m], row stride 528B (16B aligned)
    __shared__ float Bs[16][64];    // [k][n]
    int tid = threadIdx.x;
    int tx = tid & 15, ty = tid >> 4;
    int row0 = blockIdx.x * 128;

    // gmem load assignment
    int am = tid >> 1;            // 0..127: A row within tile
    int af = (tid & 1) * 8;       // k offset within BK: 0 or 8 (two float4s)
    int bk = tid >> 4;            // 0..15
    int bn = (tid & 15) * 4;
    int arow = row0 + am;
    bool a_ok = arow < N_NODES;
    const float* Abase = A + (size_t)arow * K;

    ull acc[8][2];
#pragma unroll
    for (int i = 0; i < 8; i++) { acc[i][0] = 0ull; acc[i][1] = 0ull; }

    float4 pa0, pa1, pb;
    // prologue: load tile 0
    pa0 = a_ok ? *(const float4*)&Abase[af]     : make_float4(0, 0, 0, 0);
    pa1 = a_ok ? *(const float4*)&Abase[af + 4] : make_float4(0, 0, 0, 0);
    pb  = *(const float4*)&B[bk * 64 + bn];

    for (int k0 = 0; k0 < K; k0 += 16) {
        // commit prefetched tile to smem
        As[af + 0][am] = pa0.x; As[af + 1][am] = pa0.y;
        As[af + 2][am] = pa0.z; As[af + 3][am] = pa0.w;
        As[af + 4][am] = pa1.x; As[af + 5][am] = pa1.y;
        As[af + 6][am] = pa1.z; As[af + 7][am] = pa1.w;
        *(float4*)&Bs[bk][bn] = pb;
        __syncthreads();

        // prefetch next tile (overlaps compute)
        if (k0 + 16 < K) {
            pa0 = a_ok ? *(const float4*)&Abase[k0 + 16 + af]     : make_float4(0, 0, 0, 0);
            pa1 = a_ok ? *(const float4*)&Abase[k0 + 16 + af + 4] : make_float4(0, 0, 0, 0);
            pb  = *(const float4*)&B[(k0 + 16 + bk) * 64 + bn];
        }

#pragma unroll
        for (int kk = 0; kk < 16; kk++) {
            float4 a4 = *(const float4*)&As[kk][ty * 8];
            float4 a8 = *(const float4*)&As[kk][ty * 8 + 4];
            ulonglong2 bv = *(const ulonglong2*)&Bs[kk][tx * 4];
            ull ad;
            ad = pack2(a4.x, a4.x); ffma2(acc[0][0], ad, bv.x); ffma2(acc[0][1], ad, bv.y);
            ad = pack2(a4.y, a4.y); ffma2(acc[1][0], ad, bv.x); ffma2(acc[1][1], ad, bv.y);
            ad = pack2(a4.z, a4.z); ffma2(acc[2][0], ad, bv.x); ffma2(acc[2][1], ad, bv.y);
            ad = pack2(a4.w, a4.w); ffma2(acc[3][0], ad, bv.x); ffma2(acc[3][1], ad, bv.y);
            ad = pack2(a8.x, a8.x); ffma2(acc[4][0], ad, bv.x); ffma2(acc[4][1], ad, bv.y);
            ad = pack2(a8.y, a8.y); ffma2(acc[5][0], ad, bv.x); ffma2(acc[5][1], ad, bv.y);
            ad = pack2(a8.z, a8.z); ffma2(acc[6][0], ad, bv.x); ffma2(acc[6][1], ad, bv.y);
            ad = pack2(a8.w, a8.w); ffma2(acc[7][0], ad, bv.x); ffma2(acc[7][1], ad, bv.y);
        }
        __syncthreads();
    }
#pragma unroll
    for (int i = 0; i < 8; i++) {
        int row = row0 + ty * 8 + i;
        if (row < N_NODES) {
            float2 f01 = *(float2*)&acc[i][0];
            float2 f23 = *(float2*)&acc[i][1];
            __half2 h0 = __floats2half2_rn(f01.x, f01.y);
            __half2 h1 = __floats2half2_rn(f23.x, f23.y);
            uint2 v;
            v.x = *(unsigned int*)&h0;
            v.y = *(unsigned int*)&h1;
            *(uint2*)&Hout[(size_t)row * 32 + tx * 2] = v;
        }
    }
}

// ---------------- SPMM (CSR gather fp16, 8+4 batches) + fused epilogue ----------------
__device__ __forceinline__ float warp_sum(float v) {
#pragma unroll
    for (int o = 16; o; o >>= 1) v += __shfl_xor_sync(0xffffffffu, v, o);
    return v;
}

// MODE 0: Z[g] = SELU(A@H + b) ; MODE 1: out[g] = rownorm(A@H + b)
template <int MODE>
__global__ __launch_bounds__(256) void spmm_kernel(const float* __restrict__ bias,
                                                   float* __restrict__ out_ext,
                                                   int gbase) {
    int g = gbase + blockIdx.y;
    int warp = threadIdx.x >> 5, lane = threadIdx.x & 31;
    int row = blockIdx.x * 8 + warp;
    if (row >= N_NODES) return;
    const __half2* __restrict__ H = g_H + (size_t)g * N_NODES * 32;
    int key = g * N_NODES + row;
    int s = g_rowptr[key], e = g_rowptr[key + 1];
    float bx = __ldg(&bias[lane * 2]);
    float by = __ldg(&bias[lane * 2 + 1]);
    float ax = 0.f, ay = 0.f;
    int j = s;
    for (; j + 8 <= e; j += 8) {
        int2 ed[8];
#pragma unroll
        for (int i = 0; i < 8; i++) ed[i] = g_edge[j + i];
        __half2 h[8];
#pragma unroll
        for (int i = 0; i < 8; i++)
            h[i] = H[(size_t)ed[i].x * 32 + lane];
#pragma unroll
        for (int i = 0; i < 8; i++) {
            float v = __int_as_float(ed[i].y);
            float2 f = __half22float2(h[i]);
            ax += v * f.x;
            ay += v * f.y;
        }
    }
    if (j + 4 <= e) {
        int2 ed[4];
#pragma unroll
        for (int i = 0; i < 4; i++) ed[i] = g_edge[j + i];
        __half2 h[4];
#pragma unroll
        for (int i = 0; i < 4; i++)
            h[i] = H[(size_t)ed[i].x * 32 + lane];
#pragma unroll
        for (int i = 0; i < 4; i++) {
            float v = __int_as_float(ed[i].y);
            float2 f = __half22float2(h[i]);
            ax += v * f.x;
            ay += v * f.y;
        }
        j += 4;
    }
    for (; j < e; j++) {
        int2 ed = g_edge[j];
        float v = __int_as_float(ed.y);
        float2 f = __half22float2(H[(size_t)ed.x * 32 + lane]);
        ax += v * f.x;
        ay += v * f.y;
    }
    ax += bx;
    ay += by;
    if (MODE == 0) {
        const float sc = 1.0507009873554805f, al = 1.6732632423543772f;
        ax = ax > 0.f ? sc * ax : sc * al * expm1f(ax);
        ay = ay > 0.f ? sc * ay : sc * al * expm1f(ay);
        float2 o = {ax, ay};
        *(float2*)&g_Z[((size_t)g * N_NODES + row) * HID + lane * 2] = o;
    } else {
        float ss = warp_sum(ax * ax + ay * ay);
        float inv = 1.f / fmaxf(sqrtf(ss), 1e-12f);
        float2 o = {ax * inv, ay * inv};
        *(float2*)&out_ext[((size_t)g * N_NODES + row) * HID + lane * 2] = o;
    }
}

// ---------------- launch (per-graph pipelined gemm1 + chains) ----------------
extern "C" void kernel_launch(void* const* d_in, const int* in_sizes, int n_in,
                              void* d_out, int out_size) {
    const float* X1 = (const float*)d_in[0];
    const float* X2 = (const float*)d_in[1];
    const int*   rows1 = (const int*)d_in[2];
    const int*   cols1 = (const int*)d_in[3];
    const float* vals1 = (const float*)d_in[4];
    const int*   rows2 = (const int*)d_in[5];
    const int*   cols2 = (const int*)d_in[6];
    const float* vals2 = (const float*)d_in[7];
    const float* W1 = (const float*)d_in[8];
    const float* b1 = (const float*)d_in[9];
    const float* W2 = (const float*)d_in[10];
    const float* b2 = (const float*)d_in[11];
    float* out = (float*)d_out;

    // Aux streams/events: created once on the first (uncaptured, untimed)
    // correctness call; reused on every call. Identical work every call.
    static cudaStream_t sA = nullptr, sB = nullptr, sC = nullptr;
    static cudaEvent_t evRoot = nullptr, evCsr = nullptr, evG0 = nullptr,
                       evG1 = nullptr, evA = nullptr, evB = nullptr;
    if (sA == nullptr) {
        cudaStreamCreateWithFlags(&sA, cudaStreamNonBlocking);
        cudaStreamCreateWithFlags(&sB, cudaStreamNonBlocking);
        cudaStreamCreateWithFlags(&sC, cudaStreamNonBlocking);
        cudaEventCreateWithFlags(&evRoot, cudaEventDisableTiming);
        cudaEventCreateWithFlags(&evCsr, cudaEventDisableTiming);
        cudaEventCreateWithFlags(&evG0, cudaEventDisableTiming);
        cudaEventCreateWithFlags(&evG1, cudaEventDisableTiming);
        cudaEventCreateWithFlags(&evA, cudaEventDisableTiming);
        cudaEventCreateWithFlags(&evB, cudaEventDisableTiming);
    }

    const int ZG = (NTOT + 255) / 256;          // 782
    const int EG = (2 * N_EDGES + 255) / 256;   // 9375
    dim3 GG1((N_NODES + 127) / 128, 1);         // gemm, per graph (782)
    dim3 SG1((N_NODES + 7) / 8, 1);             // spmm, per graph (12500)

    // fork: CSR chain on sC, per-graph gemm1 on main
    cudaEventRecord(evRoot, 0);
    cudaStreamWaitEvent(sC, evRoot, 0);

    zero_cnt_kernel<<<ZG, 256, 0, sC>>>();
    edge_count_kernel<<<EG, 256, 0, sC>>>(rows1, rows2);
    scan_reduce_kernel<<<NB2, 256, 0, sC>>>();

    gemm128_kernel<<<GG1, 256>>>(X1, X2, 0, W1, 256, 0);   // H_g0 (launch #4 for ncu)
    cudaEventRecord(evG0, 0);
    gemm128_kernel<<<GG1, 256>>>(X1, X2, 0, W1, 256, 1);   // H_g1
    cudaEventRecord(evG1, 0);

    scan_bsums_kernel<<<1, 256, 0, sC>>>();
    scan_final_kernel<<<NB2, 256, 0, sC>>>();              // also re-zeroes g_cnt
    edge_scatter_kernel<<<EG, 256, 0, sC>>>(rows1, cols1, vals1, rows2, cols2, vals2);
    cudaEventRecord(evCsr, sC);

    // graph-0 chain on sA (needs gemm1_g0 + CSR) — overlaps gemm1_g1
    cudaStreamWaitEvent(sA, evG0, 0);
    cudaStreamWaitEvent(sA, evCsr, 0);
    spmm_kernel<0><<<SG1, 256, 0, sA>>>(b1, nullptr, 0);
    gemm128_kernel<<<GG1, 256, 0, sA>>>(X1, X2, 1, W2, HID, 0);
    spmm_kernel<1><<<SG1, 256, 0, sA>>>(b2, out, 0);
    cudaEventRecord(evA, sA);

    // graph-1 chain on sB (needs gemm1_g1 + CSR)
    cudaStreamWaitEvent(sB, evG1, 0);
    cudaStreamWaitEvent(sB, evCsr, 0);
    spmm_kernel<0><<<SG1, 256, 0, sB>>>(b1, nullptr, 1);
    gemm128_kernel<<<GG1, 256, 0, sB>>>(X1, X2, 1, W2, HID, 1);
    spmm_kernel<1><<<SG1, 256, 0, sB>>>(b2, out, 1);
    cudaEventRecord(evB, sB);

    // join
    cudaStreamWaitEvent(0, evA, 0);
    cudaStreamWaitEvent(0, evB, 0);
}

// round 16
// speedup vs baseline: 1.1085x; 1.0370x over previous
#include <cuda_runtime.h>
#include <cuda_fp16.h>
#include <math.h>

#define N_NODES 100000
#define N_EDGES 1200000
#define HID 64
#define NTOT (2 * N_NODES)
#define NB2 196   // ceil(200000/1024)

typedef unsigned long long ull;

// ---------------- scratch (device globals, no allocation) ----------------
__device__ __half2 g_H[2 * (size_t)N_NODES * 32];   // H in fp16 (32 half2 per row)
__device__ float   g_Z[2 * (size_t)N_NODES * HID];  // post-SELU activations (fp32)
__device__ int   g_rowptr[NTOT + 1];
__device__ int2  g_edge[2 * N_EDGES];    // sorted (col, val-bits) per dest row
__device__ int   g_cnt[NTOT];
__device__ int   g_bsums[NB2 + 1];

// ---------------- packed fp32 helpers ----------------
__device__ __forceinline__ void ffma2(ull& c, ull a, ull b) {
    asm("fma.rn.f32x2 %0, %1, %2, %0;" : "+l"(c) : "l"(a), "l"(b));
}
__device__ __forceinline__ ull pack2(float x, float y) {
    ull r;
    asm("mov.b64 %0, {%1, %2};" : "=l"(r) : "f"(x), "f"(y));
    return r;
}

// ---------------- CSR build (both graphs at once) ----------------
__global__ void zero_cnt_kernel() {
    int i = blockIdx.x * 256 + threadIdx.x;
    if (i < NTOT) g_cnt[i] = 0;
}

__global__ void edge_count_kernel(const int* __restrict__ rows1,
                                  const int* __restrict__ rows2) {
    int e = blockIdx.x * 256 + threadIdx.x;
    if (e < 2 * N_EDGES) {
        int g = e >= N_EDGES;
        int le = e - g * N_EDGES;
        int r = g ? rows2[le] : rows1[le];
        atomicAdd(&g_cnt[g * N_NODES + r], 1);
    }
}

__global__ void scan_reduce_kernel() {
    __shared__ int s[256];
    int t = threadIdx.x;
    int base = blockIdx.x * 1024 + t * 4;
    int v = 0;
#pragma unroll
    for (int i = 0; i < 4; i++) {
        int idx = base + i;
        if (idx < NTOT) v += g_cnt[idx];
    }
    s[t] = v;
    __syncthreads();
    for (int o = 128; o; o >>= 1) {
        if (t < o) s[t] += s[t + o];
        __syncthreads();
    }
    if (t == 0) g_bsums[blockIdx.x] = s[0];
}

__global__ void scan_bsums_kernel() {
    __shared__ int s[2][256];
    int t = threadIdx.x;
    int v = (t < NB2) ? g_bsums[t] : 0;
    int buf = 0;
    s[0][t] = v;
    __syncthreads();
    for (int o = 1; o < 256; o <<= 1) {
        int x = s[buf][t];
        if (t >= o) x += s[buf][t - o];
        s[buf ^ 1][t] = x;
        buf ^= 1;
        __syncthreads();
    }
    int inc = s[buf][t];
    if (t < NB2) g_bsums[t] = inc - v;   // exclusive
    if (t == 255) g_bsums[NB2] = inc;    // total
}

__global__ void scan_final_kernel() {
    __shared__ int s[2][256];
    int t = threadIdx.x;
    int base = blockIdx.x * 1024 + t * 4;
    int v[4];
#pragma unroll
    for (int i = 0; i < 4; i++)
        v[i] = (base + i < NTOT) ? g_cnt[base + i] : 0;
    int tot = v[0] + v[1] + v[2] + v[3];
    int buf = 0;
    s[0][t] = tot;
    __syncthreads();
    for (int o = 1; o < 256; o <<= 1) {
        int x = s[buf][t];
        if (t >= o) x += s[buf][t - o];
        s[buf ^ 1][t] = x;
        buf ^= 1;
        __syncthreads();
    }
    int run = s[buf][t] - tot + g_bsums[blockIdx.x];
#pragma unroll
    for (int i = 0; i < 4; i++) {
        if (base + i < NTOT) {
            g_rowptr[base + i] = run;
            g_cnt[base + i] = 0;          // fused re-zero for the scatter pass
        }
        run += v[i];
    }
    if (blockIdx.x == 0 && t == 0) g_rowptr[NTOT] = g_bsums[NB2];
}

__global__ void edge_scatter_kernel(const int* __restrict__ rows1,
                                    const int* __restrict__ cols1,
                                    const float* __restrict__ vals1,
                                    const int* __restrict__ rows2,
                                    const int* __restrict__ cols2,
                                    const float* __restrict__ vals2) {
    int e = blockIdx.x * 256 + threadIdx.x;
    if (e < 2 * N_EDGES) {
        int g = e >= N_EDGES;
        int le = e - g * N_EDGES;
        int r, c; float v;
        if (g) { r = rows2[le]; c = cols2[le]; v = vals2[le]; }
        else   { r = rows1[le]; c = cols1[le]; v = vals1[le]; }
        int key = g * N_NODES + r;
        int p = g_rowptr[key] + atomicAdd(&g_cnt[key], 1);
        g_edge[p] = make_int2(c, __float_as_int(v));
    }
}

// ---------------- GEMM: H[g] = A[g] @ B[K x 64], fp16 output ----------------
// BM=128, BN=64, BK=16, 256 threads, 8 rows x 4 cols per thread, FFMA2 inner,
// register prefetch of the next gmem tile. A loads are streaming (__ldcs) to
// avoid evicting the H working set from L2.
__global__ __launch_bounds__(256) void gemm128_kernel(const float* __restrict__ X1,
                                                      const float* __restrict__ X2,
                                                      int use_z,
                                                      const float* __restrict__ B,
                                                      int K, int gbase) {
    int g = gbase + blockIdx.y;
    const float* __restrict__ A =
        use_z ? (g_Z + (size_t)g * N_NODES * HID) : (g ? X2 : X1);
    __half2* __restrict__ Hout = g_H + (size_t)g * N_NODES * 32;

    __shared__ float As[16][132];   // [k][m], row stride 528B (16B aligned)
    __shared__ float Bs[16][64];    // [k][n]
    int tid = threadIdx.x;
    int tx = tid & 15, ty = tid >> 4;
    int row0 = blockIdx.x * 128;

    // gmem load assignment
    int am = tid >> 1;            // 0..127: A row within tile
    int af = (tid & 1) * 8;       // k offset within BK: 0 or 8 (two float4s)
    int bk = tid >> 4;            // 0..15
    int bn = (tid & 15) * 4;
    int arow = row0 + am;
    bool a_ok = arow < N_NODES;
    const float* Abase = A + (size_t)arow * K;

    ull acc[8][2];
#pragma unroll
    for (int i = 0; i < 8; i++) { acc[i][0] = 0ull; acc[i][1] = 0ull; }

    float4 pa0, pa1, pb;
    // prologue: load tile 0 (streaming)
    pa0 = a_ok ? __ldcs((const float4*)&Abase[af])     : make_float4(0, 0, 0, 0);
    pa1 = a_ok ? __ldcs((const float4*)&Abase[af + 4]) : make_float4(0, 0, 0, 0);
    pb  = *(const float4*)&B[bk * 64 + bn];

    for (int k0 = 0; k0 < K; k0 += 16) {
        // commit prefetched tile to smem
        As[af + 0][am] = pa0.x; As[af + 1][am] = pa0.y;
        As[af + 2][am] = pa0.z; As[af + 3][am] = pa0.w;
        As[af + 4][am] = pa1.x; As[af + 5][am] = pa1.y;
        As[af + 6][am] = pa1.z; As[af + 7][am] = pa1.w;
        *(float4*)&Bs[bk][bn] = pb;
        __syncthreads();

        // prefetch next tile (overlaps compute, streaming)
        if (k0 + 16 < K) {
            pa0 = a_ok ? __ldcs((const float4*)&Abase[k0 + 16 + af])     : make_float4(0, 0, 0, 0);
            pa1 = a_ok ? __ldcs((const float4*)&Abase[k0 + 16 + af + 4]) : make_float4(0, 0, 0, 0);
            pb  = *(const float4*)&B[(k0 + 16 + bk) * 64 + bn];
        }

#pragma unroll
        for (int kk = 0; kk < 16; kk++) {
            float4 a4 = *(const float4*)&As[kk][ty * 8];
            float4 a8 = *(const float4*)&As[kk][ty * 8 + 4];
            ulonglong2 bv = *(const ulonglong2*)&Bs[kk][tx * 4];
            ull ad;
            ad = pack2(a4.x, a4.x); ffma2(acc[0][0], ad, bv.x); ffma2(acc[0][1], ad, bv.y);
            ad = pack2(a4.y, a4.y); ffma2(acc[1][0], ad, bv.x); ffma2(acc[1][1], ad, bv.y);
            ad = pack2(a4.z, a4.z); ffma2(acc[2][0], ad, bv.x); ffma2(acc[2][1], ad, bv.y);
            ad = pack2(a4.w, a4.w); ffma2(acc[3][0], ad, bv.x); ffma2(acc[3][1], ad, bv.y);
            ad = pack2(a8.x, a8.x); ffma2(acc[4][0], ad, bv.x); ffma2(acc[4][1], ad, bv.y);
            ad = pack2(a8.y, a8.y); ffma2(acc[5][0], ad, bv.x); ffma2(acc[5][1], ad, bv.y);
            ad = pack2(a8.z, a8.z); ffma2(acc[6][0], ad, bv.x); ffma2(acc[6][1], ad, bv.y);
            ad = pack2(a8.w, a8.w); ffma2(acc[7][0], ad, bv.x); ffma2(acc[7][1], ad, bv.y);
        }
        __syncthreads();
    }
#pragma unroll
    for (int i = 0; i < 8; i++) {
        int row = row0 + ty * 8 + i;
        if (row < N_NODES) {
            float2 f01 = *(float2*)&acc[i][0];
            float2 f23 = *(float2*)&acc[i][1];
            __half2 h0 = __floats2half2_rn(f01.x, f01.y);
            __half2 h1 = __floats2half2_rn(f23.x, f23.y);
            uint2 v;
            v.x = *(unsigned int*)&h0;
            v.y = *(unsigned int*)&h1;
            *(uint2*)&Hout[(size_t)row * 32 + tx * 2] = v;   // keep H in L2
        }
    }
}

// ---------------- SPMM (CSR gather fp16, 8+4 batches) + fused epilogue -------
// Edge loads streaming (__ldcs), Z/out writes streaming (__stcs): protect the
// H working set in L2; H gathers use default caching.
__device__ __forceinline__ float warp_sum(float v) {
#pragma unroll
    for (int o = 16; o; o >>= 1) v += __shfl_xor_sync(0xffffffffu, v, o);
    return v;
}

// MODE 0: Z[g] = SELU(A@H + b) ; MODE 1: out[g] = rownorm(A@H + b)
template <int MODE>
__global__ __launch_bounds__(256) void spmm_kernel(const float* __restrict__ bias,
                                                   float* __restrict__ out_ext,
                                                   int gbase) {
    int g = gbase + blockIdx.y;
    int warp = threadIdx.x >> 5, lane = threadIdx.x & 31;
    int row = blockIdx.x * 8 + warp;
    if (row >= N_NODES) return;
    const __half2* __restrict__ H = g_H + (size_t)g * N_NODES * 32;
    int key = g * N_NODES + row;
    int s = g_rowptr[key], e = g_rowptr[key + 1];
    float bx = __ldg(&bias[lane * 2]);
    float by = __ldg(&bias[lane * 2 + 1]);
    float ax = 0.f, ay = 0.f;
    int j = s;
    for (; j + 8 <= e; j += 8) {
        int2 ed[8];
#pragma unroll
        for (int i = 0; i < 8; i++) ed[i] = __ldcs(&g_edge[j + i]);
        __half2 h[8];
#pragma unroll
        for (int i = 0; i < 8; i++)
            h[i] = H[(size_t)ed[i].x * 32 + lane];
#pragma unroll
        for (int i = 0; i < 8; i++) {
            float v = __int_as_float(ed[i].y);
            float2 f = __half22float2(h[i]);
            ax += v * f.x;
            ay += v * f.y;
        }
    }
    if (j + 4 <= e) {
        int2 ed[4];
#pragma unroll
        for (int i = 0; i < 4; i++) ed[i] = __ldcs(&g_edge[j + i]);
        __half2 h[4];
#pragma unroll
        for (int i = 0; i < 4; i++)
            h[i] = H[(size_t)ed[i].x * 32 + lane];
#pragma unroll
        for (int i = 0; i < 4; i++) {
            float v = __int_as_float(ed[i].y);
            float2 f = __half22float2(h[i]);
            ax += v * f.x;
            ay += v * f.y;
        }
        j += 4;
    }
    for (; j < e; j++) {
        int2 ed = __ldcs(&g_edge[j]);
        float v = __int_as_float(ed.y);
        float2 f = __half22float2(H[(size_t)ed.x * 32 + lane]);
        ax += v * f.x;
        ay += v * f.y;
    }
    ax += bx;
    ay += by;
    if (MODE == 0) {
        const float sc = 1.0507009873554805f, al = 1.6732632423543772f;
        ax = ax > 0.f ? sc * ax : sc * al * expm1f(ax);
        ay = ay > 0.f ? sc * ay : sc * al * expm1f(ay);
        float2 o = {ax, ay};
        __stcs((float2*)&g_Z[((size_t)g * N_NODES + row) * HID + lane * 2], o);
    } else {
        float ss = warp_sum(ax * ax + ay * ay);
        float inv = 1.f / fmaxf(sqrtf(ss), 1e-12f);
        float2 o = {ax * inv, ay * inv};
        __stcs((float2*)&out_ext[((size_t)g * N_NODES + row) * HID + lane * 2], o);
    }
}

// ---------------- launch (per-graph pipelined gemm1 + chains) ----------------
extern "C" void kernel_launch(void* const* d_in, const int* in_sizes, int n_in,
                              void* d_out, int out_size) {
    const float* X1 = (const float*)d_in[0];
    const float* X2 = (const float*)d_in[1];
    const int*   rows1 = (const int*)d_in[2];
    const int*   cols1 = (const int*)d_in[3];
    const float* vals1 = (const float*)d_in[4];
    const int*   rows2 = (const int*)d_in[5];
    const int*   cols2 = (const int*)d_in[6];
    const float* vals2 = (const float*)d_in[7];
    const float* W1 = (const float*)d_in[8];
    const float* b1 = (const float*)d_in[9];
    const float* W2 = (const float*)d_in[10];
    const float* b2 = (const float*)d_in[11];
    float* out = (float*)d_out;

    // Aux streams/events: created once on the first (uncaptured, untimed)
    // correctness call; reused on every call. Identical work every call.
    static cudaStream_t sA = nullptr, sB = nullptr, sC = nullptr;
    static cudaEvent_t evRoot = nullptr, evCsr = nullptr, evG0 = nullptr,
                       evG1 = nullptr, evA = nullptr, evB = nullptr;
    if (sA == nullptr) {
        cudaStreamCreateWithFlags(&sA, cudaStreamNonBlocking);
        cudaStreamCreateWithFlags(&sB, cudaStreamNonBlocking);
        cudaStreamCreateWithFlags(&sC, cudaStreamNonBlocking);
        cudaEventCreateWithFlags(&evRoot, cudaEventDisableTiming);
        cudaEventCreateWithFlags(&evCsr, cudaEventDisableTiming);
        cudaEventCreateWithFlags(&evG0, cudaEventDisableTiming);
        cudaEventCreateWithFlags(&evG1, cudaEventDisableTiming);
        cudaEventCreateWithFlags(&evA, cudaEventDisableTiming);
        cudaEventCreateWithFlags(&evB, cudaEventDisableTiming);
    }

    const int ZG = (NTOT + 255) / 256;          // 782
    const int EG = (2 * N_EDGES + 255) / 256;   // 9375
    dim3 GG1((N_NODES + 127) / 128, 1);         // gemm, per graph (782)
    dim3 SG1((N_NODES + 7) / 8, 1);             // spmm, per graph (12500)

    // fork: CSR chain on sC, per-graph gemm1 on main
    cudaEventRecord(evRoot, 0);
    cudaStreamWaitEvent(sC, evRoot, 0);

    zero_cnt_kernel<<<ZG, 256, 0, sC>>>();
    edge_count_kernel<<<EG, 256, 0, sC>>>(rows1, rows2);
    scan_reduce_kernel<<<NB2, 256, 0, sC>>>();

    gemm128_kernel<<<GG1, 256>>>(X1, X2, 0, W1, 256, 0);   // H_g0 (launch #4 for ncu)
    cudaEventRecord(evG0, 0);
    gemm128_kernel<<<GG1, 256>>>(X1, X2, 0, W1, 256, 1);   // H_g1
    cudaEventRecord(evG1, 0);

    scan_bsums_kernel<<<1, 256, 0, sC>>>();
    scan_final_kernel<<<NB2, 256, 0, sC>>>();              // also re-zeroes g_cnt
    edge_scatter_kernel<<<EG, 256, 0, sC>>>(rows1, cols1, vals1, rows2, cols2, vals2);
    cudaEventRecord(evCsr, sC);

    // graph-0 chain on sA (needs gemm1_g0 + CSR) — overlaps gemm1_g1
    cudaStreamWaitEvent(sA, evG0, 0);
    cudaStreamWaitEvent(sA, evCsr, 0);
    spmm_kernel<0><<<SG1, 256, 0, sA>>>(b1, nullptr, 0);
    gemm128_kernel<<<GG1, 256, 0, sA>>>(X1, X2, 1, W2, HID, 0);
    spmm_kernel<1><<<SG1, 256, 0, sA>>>(b2, out, 0);
    cudaEventRecord(evA, sA);

    // graph-1 chain on sB (needs gemm1_g1 + CSR)
    cudaStreamWaitEvent(sB, evG1, 0);
    cudaStreamWaitEvent(sB, evCsr, 0);
    spmm_kernel<0><<<SG1, 256, 0, sB>>>(b1, nullptr, 1);
    gemm128_kernel<<<GG1, 256, 0, sB>>>(X1, X2, 1, W2, HID, 1);
    spmm_kernel<1><<<SG1, 256, 0, sB>>>(b2, out, 1);
    cudaEventRecord(evB, sB);

    // join
    cudaStreamWaitEvent(0, evA, 0);
    cudaStreamWaitEvent(0, evB, 0);
}